// round 1
// baseline (speedup 1.0000x reference)
#include <cuda_runtime.h>

#define Nn 8
#define Cc 64
#define Hh 256
#define Ww 256
#define Pp 8          // CTAs per cluster (per batch)
#define WC 32         // columns per CTA
#define FSTR 34       // fbuf row stride (WC + 2 halo)
#define NT 256

// f-stack scratch (forward results, consumed by backward pass): 134 MB
__device__ float g_stack[(size_t)Nn * Cc * Hh * Ww];

extern __shared__ float sm[];

__device__ __forceinline__ void csync() {
    asm volatile("barrier.cluster.arrive.aligned;" ::: "memory");
    asm volatile("barrier.cluster.wait.aligned;" ::: "memory");
}

__device__ __forceinline__ float ld_dsmem(const float* p, unsigned rank) {
    unsigned a = (unsigned)__cvta_generic_to_shared(p);
    unsigned ra;
    asm volatile("mapa.shared::cluster.u32 %0, %1, %2;" : "=r"(ra) : "r"(a), "r"(rank));
    float v;
    asm volatile("ld.shared::cluster.f32 %0, [%1];" : "=f"(v) : "r"(ra));
    return v;
}

// One scan step: y = conv1d(f_prev) ; instance-norm over full row ; ELU ; += src[row]
// Writes new f into fb (SMEM) and to dst (GMEM).
__device__ __forceinline__ void step_row(
    float* __restrict__ fb, const float* __restrict__ Ws,
    float* __restrict__ mail, float* __restrict__ mr,
    const float* __restrict__ src, float* __restrict__ dst,
    int row, int tid, int lane, int warp, int ob, int w0, unsigned rank)
{
    // barrier 1: previous-row f complete in every CTA of the cluster
    csync();

    // halo exchange via DSMEM (1 column each side, 64 channels)
    if (tid < 64) {
        if (rank > 0)
            fb[tid * FSTR] = ld_dsmem(&fb[tid * FSTR + WC], rank - 1);
    } else if (tid < 128) {
        int ch = tid - 64;
        if (rank < Pp - 1)
            fb[ch * FSTR + WC + 1] = ld_dsmem(&fb[ch * FSTR + 1], rank + 1);
    }

    // prefetch residual row (hidden under conv)
    float xr[8];
    const size_t rbase = (size_t)row * Ww + w0 + lane;
#pragma unroll
    for (int t = 0; t < 8; t++)
        xr[t] = src[(size_t)(ob + t) * (Hh * Ww) + rbase];

    __syncthreads();  // halos visible CTA-wide

    // conv: lane = column, warp owns 8 output channels [ob, ob+8)
    float acc[8];
#pragma unroll
    for (int t = 0; t < 8; t++) acc[t] = 0.f;

#pragma unroll 4
    for (int i = 0; i < Cc; i++) {
        float a0 = fb[i * FSTR + lane];
        float a1 = fb[i * FSTR + lane + 1];
        float a2 = fb[i * FSTR + lane + 2];
        const float* wp = Ws + i * 192 + ob;   // rows: k = i*3 + kx, 64 floats each
        float4 u0 = *(const float4*)(wp);          // kx=0, o..o+3
        float4 u1 = *(const float4*)(wp + 4);      // kx=0, o+4..o+7
        float4 v0 = *(const float4*)(wp + 64);     // kx=1
        float4 v1 = *(const float4*)(wp + 68);
        float4 t0 = *(const float4*)(wp + 128);    // kx=2
        float4 t1 = *(const float4*)(wp + 132);
        acc[0] = fmaf(a0, u0.x, acc[0]); acc[0] = fmaf(a1, v0.x, acc[0]); acc[0] = fmaf(a2, t0.x, acc[0]);
        acc[1] = fmaf(a0, u0.y, acc[1]); acc[1] = fmaf(a1, v0.y, acc[1]); acc[1] = fmaf(a2, t0.y, acc[1]);
        acc[2] = fmaf(a0, u0.z, acc[2]); acc[2] = fmaf(a1, v0.z, acc[2]); acc[2] = fmaf(a2, t0.z, acc[2]);
        acc[3] = fmaf(a0, u0.w, acc[3]); acc[3] = fmaf(a1, v0.w, acc[3]); acc[3] = fmaf(a2, t0.w, acc[3]);
        acc[4] = fmaf(a0, u1.x, acc[4]); acc[4] = fmaf(a1, v1.x, acc[4]); acc[4] = fmaf(a2, t1.x, acc[4]);
        acc[5] = fmaf(a0, u1.y, acc[5]); acc[5] = fmaf(a1, v1.y, acc[5]); acc[5] = fmaf(a2, t1.y, acc[5]);
        acc[6] = fmaf(a0, u1.z, acc[6]); acc[6] = fmaf(a1, v1.z, acc[6]); acc[6] = fmaf(a2, t1.z, acc[6]);
        acc[7] = fmaf(a0, u1.w, acc[7]); acc[7] = fmaf(a1, v1.w, acc[7]); acc[7] = fmaf(a2, t1.w, acc[7]);
    }

    // per-warp reduction over this CTA's 32 columns (warp covers all of its channels' cols)
    float s[8], q[8];
#pragma unroll
    for (int t = 0; t < 8; t++) { s[t] = acc[t]; q[t] = acc[t] * acc[t]; }
#pragma unroll
    for (int off = 16; off >= 1; off >>= 1) {
#pragma unroll
        for (int t = 0; t < 8; t++) {
            s[t] += __shfl_xor_sync(0xffffffffu, s[t], off);
            q[t] += __shfl_xor_sync(0xffffffffu, q[t], off);
        }
    }
    if (lane == 0) {
#pragma unroll
        for (int t = 0; t < 8; t++) { mail[ob + t] = s[t]; mail[64 + ob + t] = q[t]; }
    }

    // barrier 2: partial sums published cluster-wide
    csync();

    // cross-CTA reduction of sum / sumsq (lanes 0..7: sum, 8..15: sumsq)
    float tot = 0.f;
    if (lane < 16) {
        const float* mp = mail + (lane >> 3) * 64 + ob + (lane & 7);
#pragma unroll
        for (unsigned p = 0; p < Pp; p++) tot += ld_dsmem(mp, p);
    }
    float other = __shfl_sync(0xffffffffu, tot, (lane & 7) + 8);
    if (lane < 8) {
        float mean = tot * (1.0f / (float)Ww);
        float var  = other * (1.0f / (float)Ww) - mean * mean;
        float rstd = rsqrtf(var + 1e-5f);
        mr[warp * 16 + lane]     = mean;
        mr[warp * 16 + 8 + lane] = rstd;
    }
    __syncwarp();

    // normalize + ELU + residual; write new f (SMEM) and row output (GMEM)
#pragma unroll
    for (int t = 0; t < 8; t++) {
        float mean = mr[warp * 16 + t];
        float rstd = mr[warp * 16 + 8 + t];
        float v = (acc[t] - mean) * rstd;
        v = v > 0.f ? v : expm1f(v);
        float fn = v + xr[t];
        fb[(ob + t) * FSTR + 1 + lane] = fn;
        dst[(size_t)(ob + t) * (Hh * Ww) + rbase] = fn;
    }
}

__global__ void __launch_bounds__(NT, 1) __cluster_dims__(Pp, 1, 1)
dirconv_kernel(const float* __restrict__ x, const float* __restrict__ Wg,
               float* __restrict__ out)
{
    float* Ws   = sm;                 // [192][64]  (k = i*3+kx major, o contiguous)
    float* fb   = sm + 12288;         // [64][FSTR] row state with halo cols 0 and WC+1
    float* mail = fb + Cc * FSTR;     // [2][64] per-CTA partial sum / sumsq
    float* mr   = mail + 128;         // [8 warps][16] mean/rstd scratch

    const int tid  = threadIdx.x;
    const int lane = tid & 31;
    const int warp = tid >> 5;
    const int ob   = warp * 8;
    unsigned rank;
    asm("mov.u32 %0, %%cluster_ctarank;" : "=r"(rank));
    const int b  = blockIdx.x / Pp;
    const int w0 = (int)rank * WC;

    const float* xb = x + (size_t)b * Cc * Hh * Ww;
    float* stk      = g_stack + (size_t)b * Cc * Hh * Ww;
    float* outb     = out + (size_t)b * Cc * Hh * Ww;

    // load effective weights: Ws[(i*3+kx)*64 + o] = W[o][i][1][kx]  (bias cancels in IN)
    for (int idx = tid; idx < Cc * Cc * 3; idx += NT) {
        int o = idx / (Cc * 3);
        int rem = idx - o * (Cc * 3);
        int i = rem / 3, kx = rem - i * 3;
        Ws[(i * 3 + kx) * 64 + o] = Wg[o * (Cc * 9) + i * 9 + 3 + kx];
    }
    // zero the (global-edge) halo columns once; interiors only get overwritten
    if (tid < 64) { fb[tid * FSTR] = 0.f; fb[tid * FSTR + WC + 1] = 0.f; }

    // row 0: f = x[0]
#pragma unroll
    for (int t = 0; t < 8; t++) {
        int ch = ob + t;
        float v = xb[(size_t)ch * (Hh * Ww) + w0 + lane];
        fb[ch * FSTR + 1 + lane] = v;
        stk[(size_t)ch * (Hh * Ww) + w0 + lane] = v;
    }

    // forward scan: f[i] = step(f[i-1]) + x[i], stored to stack
    for (int row = 1; row < Hh; ++row)
        step_row(fb, Ws, mail, mr, xb, stk, row, tid, lane, warp, ob, w0, rank);

    // backward init: g[H-1] = f[H-1] (already in fb, written by this very thread)
#pragma unroll
    for (int t = 0; t < 8; t++) {
        int ch = ob + t;
        outb[(size_t)ch * (Hh * Ww) + (size_t)(Hh - 1) * Ww + w0 + lane] =
            fb[ch * FSTR + 1 + lane];
    }

    // backward scan: g[p] = step(g[p+1]) + f[p], stored to out
    for (int row = Hh - 2; row >= 0; --row)
        step_row(fb, Ws, mail, mr, stk, outb, row, tid, lane, warp, ob, w0, rank);

    // keep SMEM alive until all peers are done with DSMEM reads
    csync();
}

extern "C" void kernel_launch(void* const* d_in, const int* in_sizes, int n_in,
                              void* d_out, int out_size)
{
    (void)in_sizes; (void)n_in; (void)out_size;
    const float* x  = (const float*)d_in[0];
    const float* Wg = (const float*)d_in[1];
    // d_in[2] (bias) is provably a no-op through InstanceNorm — skipped.
    float* out = (float*)d_out;

    const size_t smem = (size_t)(12288 + Cc * FSTR + 128 + 128) * sizeof(float); // 58880 B

    cudaStreamCaptureStatus cs = cudaStreamCaptureStatusNone;
    cudaStreamIsCapturing(0, &cs);
    if (cs == cudaStreamCaptureStatusNone)
        cudaFuncSetAttribute(dirconv_kernel,
                             cudaFuncAttributeMaxDynamicSharedMemorySize, (int)smem);

    dirconv_kernel<<<Nn * Pp, NT, smem>>>(x, Wg, out);
}

// round 2
// speedup vs baseline: 1.0644x; 1.0644x over previous
#include <cuda_runtime.h>

#define Nn 8
#define Cc 64
#define Hh 256
#define Ww 256
#define Pp 16          // CTAs per cluster: 8 col-groups x 2 ch-groups
#define WC 32          // columns per CTA
#define FSTR 34        // fb row stride (WC + 2 halo)
#define NT 128         // 4 warps; warp = 8 output channels x 32 cols
#define HW (Hh*Ww)

// forward-pass stack (consumed by backward pass): 134 MB
__device__ float g_stack[(size_t)Nn * Cc * Hh * Ww];

extern __shared__ float sm[];

__device__ __forceinline__ void csync() {
    asm volatile("barrier.cluster.arrive.aligned;" ::: "memory");
    asm volatile("barrier.cluster.wait.aligned;" ::: "memory");
}

__device__ __forceinline__ unsigned mapa_rank(const void* p, unsigned rank) {
    unsigned a = (unsigned)__cvta_generic_to_shared(p), ra;
    asm("mapa.shared::cluster.u32 %0, %1, %2;" : "=r"(ra) : "r"(a), "r"(rank));
    return ra;
}
__device__ __forceinline__ void st_cluster(unsigned addr, float v) {
    asm volatile("st.shared::cluster.f32 [%0], %1;" :: "r"(addr), "f"(v) : "memory");
}
__device__ __forceinline__ float ld_cluster(unsigned addr) {
    float v;
    asm volatile("ld.shared::cluster.f32 %0, [%1];" : "=f"(v) : "r"(addr));
    return v;
}

// ---- packed f32x2 helpers ----
__device__ __forceinline__ unsigned long long splat2(float a) {
    unsigned long long r;
    unsigned u = __float_as_uint(a);
    asm("mov.b64 %0, {%1, %1};" : "=l"(r) : "r"(u));
    return r;
}
__device__ __forceinline__ void fma2(unsigned long long& d, unsigned long long a, unsigned long long b) {
    asm("fma.rn.f32x2 %0, %1, %2, %0;" : "+l"(d) : "l"(a), "l"(b));
}
__device__ __forceinline__ unsigned long long add2(unsigned long long a, unsigned long long b) {
    unsigned long long d;
    asm("add.rn.f32x2 %0, %1, %2;" : "=l"(d) : "l"(a), "l"(b));
    return d;
}
__device__ __forceinline__ unsigned long long mul2(unsigned long long a, unsigned long long b) {
    unsigned long long d;
    asm("mul.rn.f32x2 %0, %1, %2;" : "=l"(d) : "l"(a), "l"(b));
    return d;
}
__device__ __forceinline__ void unpack2(unsigned long long v, float& lo, float& hi) {
    unsigned ul, uh;
    asm("mov.b64 {%0, %1}, %2;" : "=r"(ul), "=r"(uh) : "l"(v));
    lo = __uint_as_float(ul); hi = __uint_as_float(uh);
}

// One scan step. fb holds full 64ch x 34col input tile (local). This CTA
// computes its 32 output channels over its 32 cols, then push-publishes the
// new row to itself + channel-partner + column-neighbor halos via DSMEM.
__device__ __forceinline__ void step_row(
    float* __restrict__ fb, const float* __restrict__ Ws,
    float* __restrict__ mail, float* __restrict__ mr,
    const float* __restrict__ src, float* __restrict__ dst,
    int row, int lane, int ob, int cbase, int w0,
    unsigned rank, unsigned fb_partner,
    unsigned eL0, unsigned eL1, unsigned eR0, unsigned eR1,
    int hasL, int hasR, const unsigned* __restrict__ mb, int tid)
{
    // barrier #1: previous row fully published cluster-wide
    csync();

    // prefetch residual row (hidden under conv)
    float xr[8];
    const size_t rb = (size_t)row * Ww + w0 + lane;
#pragma unroll
    for (int k = 0; k < 8; k++)
        xr[k] = src[(size_t)(cbase + ob + k) * HW + rb];

    // conv: lane = col, thread owns 8 output channels as 4 f32x2 pairs
    unsigned long long acc[4] = {0ull, 0ull, 0ull, 0ull};
#pragma unroll 8
    for (int i = 0; i < Cc; i++) {
        float a0 = fb[i * FSTR + lane];
        float a1 = fb[i * FSTR + lane + 1];
        float a2 = fb[i * FSTR + lane + 2];
        unsigned long long s0 = splat2(a0), s1 = splat2(a1), s2 = splat2(a2);
        const ulonglong2* wp = (const ulonglong2*)(Ws + i * 96 + ob);
        ulonglong2 wa = wp[0],  wb = wp[1];    // tap 0: outs 0-3, 4-7 (pairs)
        ulonglong2 wc = wp[8],  wd = wp[9];    // tap 1 (+32 floats)
        ulonglong2 we = wp[16], wf2 = wp[17];  // tap 2 (+64 floats)
        fma2(acc[0], s0, wa.x); fma2(acc[1], s0, wa.y);
        fma2(acc[2], s0, wb.x); fma2(acc[3], s0, wb.y);
        fma2(acc[0], s1, wc.x); fma2(acc[1], s1, wc.y);
        fma2(acc[2], s1, wd.x); fma2(acc[3], s1, wd.y);
        fma2(acc[0], s2, we.x); fma2(acc[1], s2, we.y);
        fma2(acc[2], s2, wf2.x); fma2(acc[3], s2, wf2.y);
    }

    // per-warp reduction over this CTA's 32 cols (packed pairs)
    unsigned long long s[4], q[4];
#pragma unroll
    for (int j = 0; j < 4; j++) { s[j] = acc[j]; q[j] = mul2(acc[j], acc[j]); }
#pragma unroll
    for (int off = 16; off >= 1; off >>= 1) {
#pragma unroll
        for (int j = 0; j < 4; j++) {
            s[j] = add2(s[j], __shfl_xor_sync(0xffffffffu, s[j], off));
            q[j] = add2(q[j], __shfl_xor_sync(0xffffffffu, q[j], off));
        }
    }
    if (lane == 0) {
#pragma unroll
        for (int j = 0; j < 4; j++) {
            float lo, hi;
            unpack2(s[j], lo, hi); mail[ob + 2*j] = lo;      mail[ob + 2*j + 1] = hi;
            unpack2(q[j], lo, hi); mail[32 + ob + 2*j] = lo; mail[32 + ob + 2*j + 1] = hi;
        }
    }

    // barrier #2: conv reads done everywhere (safe to overwrite fb), mail visible
    csync();

    // cross-CTA norm reduction: 8 column-CTAs of the same ch-group
    if (tid < 32) {
        float sv = 0.f, qv = 0.f;
#pragma unroll
        for (int gg = 0; gg < 8; gg++) {
            sv += ld_cluster(mb[gg] + tid * 4u);
            qv += ld_cluster(mb[gg] + (32u + tid) * 4u);
        }
        float mean = sv * (1.f / 256.f);
        float var  = qv * (1.f / 256.f) - mean * mean;
        mr[tid]      = mean;
        mr[32 + tid] = rsqrtf(var + 1e-5f);
    }
    __syncthreads();

    // epilogue: normalize + ELU + residual; publish new row (local+remote)
    float av[8];
#pragma unroll
    for (int j = 0; j < 4; j++) unpack2(acc[j], av[2*j], av[2*j + 1]);
#pragma unroll
    for (int k = 0; k < 8; k++) {
        int chl = ob + k;
        float m = mr[chl], r = mr[32 + chl];
        float v = (av[k] - m) * r;
        v = v > 0.f ? v : expm1f(v);
        float fn = v + xr[k];
        int chg = cbase + chl;
        unsigned off = (unsigned)(chg * FSTR + 1 + lane) * 4u;
        fb[chg * FSTR + 1 + lane] = fn;
        st_cluster(fb_partner + off, fn);
        if (lane == 0 && hasL) {
            unsigned ho = (unsigned)(chg * FSTR + 33) * 4u;
            st_cluster(eL0 + ho, fn); st_cluster(eL1 + ho, fn);
        }
        if (lane == 31 && hasR) {
            unsigned ho = (unsigned)(chg * FSTR + 0) * 4u;
            st_cluster(eR0 + ho, fn); st_cluster(eR1 + ho, fn);
        }
        dst[(size_t)chg * HW + rb] = fn;
    }
}

__global__ void __launch_bounds__(NT, 1) __cluster_dims__(Pp, 1, 1)
dirconv_kernel(const float* __restrict__ x, const float* __restrict__ Wg,
               float* __restrict__ out)
{
    float* Ws   = sm;          // [64 in][3 tap][32 out]  = 6144 floats
    float* fb   = sm + 6144;   // [64 ch][34]             = 2176
    float* mail = sm + 8320;   // [sum 32 | sumsq 32]
    float* mr   = sm + 8384;   // [mean 32 | rstd 32]

    const int tid  = threadIdx.x;
    const int lane = tid & 31;
    const int warp = tid >> 5;
    const int ob   = warp * 8;           // local out-channel base of this warp
    unsigned rank;
    asm("mov.u32 %0, %%cluster_ctarank;" : "=r"(rank));
    const int g      = (int)(rank >> 1);       // column group 0..7
    const int cbase  = (int)(rank & 1u) * 32;  // global ch base of this CTA
    const int w0     = g * WC;
    const int b      = blockIdx.x / Pp;
    const unsigned basr = rank & ~1u;
    const int hasL = (g > 0), hasR = (g < 7);

    const float* xb = x + (size_t)b * Cc * HW;
    float* stk      = g_stack + (size_t)b * Cc * HW;
    float* outb     = out + (size_t)b * Cc * HW;

    // precomputed DSMEM base addresses
    const unsigned fb_partner = mapa_rank(fb, rank ^ 1u);
    const unsigned eL0 = hasL ? mapa_rank(fb, basr - 2u) : 0u;
    const unsigned eL1 = hasL ? mapa_rank(fb, basr - 1u) : 0u;
    const unsigned eR0 = hasR ? mapa_rank(fb, basr + 2u) : 0u;
    const unsigned eR1 = hasR ? mapa_rank(fb, basr + 3u) : 0u;
    unsigned mb[8];
#pragma unroll
    for (int gg = 0; gg < 8; gg++)
        mb[gg] = mapa_rank(mail, 2u * (unsigned)gg + (rank & 1u));

    // stage weights: Ws[i*96 + tap*32 + ol] = W[cbase+ol][i][1][tap] (bias cancels in IN)
    for (int idx = tid; idx < 6144; idx += NT) {
        int i   = idx / 96;
        int rem = idx - i * 96;
        int tap = rem >> 5;
        int ol  = rem & 31;
        Ws[idx] = Wg[(size_t)(cbase + ol) * 576 + i * 9 + 3 + tap];
    }
    // zero cluster-edge halos (never written by a neighbor)
    if (g == 0 && tid < 64) fb[tid * FSTR] = 0.f;
    if (g == 7 && tid < 64) fb[tid * FSTR + 33] = 0.f;

    // row 0: f = x[0] — local writes first
    float v0[8];
#pragma unroll
    for (int k = 0; k < 8; k++) {
        int chg = cbase + ob + k;
        v0[k] = xb[(size_t)chg * HW + w0 + lane];
        fb[chg * FSTR + 1 + lane] = v0[k];
        stk[(size_t)chg * HW + w0 + lane] = v0[k];
    }
    csync();  // peers alive; zero-init done everywhere before remote pushes
#pragma unroll
    for (int k = 0; k < 8; k++) {
        int chg = cbase + ob + k;
        unsigned off = (unsigned)(chg * FSTR + 1 + lane) * 4u;
        st_cluster(fb_partner + off, v0[k]);
        if (lane == 0 && hasL) {
            unsigned ho = (unsigned)(chg * FSTR + 33) * 4u;
            st_cluster(eL0 + ho, v0[k]); st_cluster(eL1 + ho, v0[k]);
        }
        if (lane == 31 && hasR) {
            unsigned ho = (unsigned)(chg * FSTR + 0) * 4u;
            st_cluster(eR0 + ho, v0[k]); st_cluster(eR1 + ho, v0[k]);
        }
    }

    // forward scan: f[i] = step(f[i-1]) + x[i], stored to stack
    for (int row = 1; row < Hh; ++row)
        step_row(fb, Ws, mail, mr, xb, stk, row, lane, ob, cbase, w0,
                 rank, fb_partner, eL0, eL1, eR0, eR1, hasL, hasR, mb, tid);

    // out row H-1 = f[H-1] (own rows are in local fb, written by this thread)
#pragma unroll
    for (int k = 0; k < 8; k++) {
        int chg = cbase + ob + k;
        outb[(size_t)chg * HW + (size_t)(Hh - 1) * Ww + w0 + lane] =
            fb[chg * FSTR + 1 + lane];
    }

    // backward scan: g[p] = step(g[p+1]) + f[p], stored to out
    for (int row = Hh - 2; row >= 0; --row)
        step_row(fb, Ws, mail, mr, stk, outb, row, lane, ob, cbase, w0,
                 rank, fb_partner, eL0, eL1, eR0, eR1, hasL, hasR, mb, tid);

    // no CTA exits while peers' remote stores may still target our SMEM
    csync();
}

extern "C" void kernel_launch(void* const* d_in, const int* in_sizes, int n_in,
                              void* d_out, int out_size)
{
    (void)in_sizes; (void)n_in; (void)out_size;
    const float* x  = (const float*)d_in[0];
    const float* Wg = (const float*)d_in[1];
    // d_in[2] (bias) cancels through InstanceNorm — skipped.
    float* out = (float*)d_out;

    const size_t smem = (size_t)(6144 + 2176 + 64 + 64) * sizeof(float); // 33792 B

    cudaStreamCaptureStatus cs = cudaStreamCaptureStatusNone;
    cudaStreamIsCapturing(0, &cs);
    if (cs == cudaStreamCaptureStatusNone) {
        cudaFuncSetAttribute(dirconv_kernel,
                             cudaFuncAttributeNonPortableClusterSizeAllowed, 1);
        cudaFuncSetAttribute(dirconv_kernel,
                             cudaFuncAttributeMaxDynamicSharedMemorySize, (int)smem);
    }

    dirconv_kernel<<<Nn * Pp, NT, (int)smem>>>(x, Wg, out);
}